// round 14
// baseline (speedup 1.0000x reference)
#include <cuda_runtime.h>
#include <math.h>

// EntropyLoss: x [R=65536, C=1024] f32 row-major.
//   n_j  = max( sqrt(sum_i x_ij^2), 1e-12 )
//   out  = -(1/R) * sum_j (1/n_j) * [ sum_i x*ln(x) - ln(n_j) * sum_i x ]
// (eps=1e-8 inside the reference log contributes <1e-6 relative error; dropped)
//
// R14: isolate the one variable R13 confounded. Keep GRID-STRIDED rows
// (R13 proved contiguous block ownership destroys TLB/page locality: 55%)
// but make each CTA consume FULL 4KB rows (GRID_Y=1, thread t owns cols
// 4t..4t+3), so every DRAM row is activated once by one CTA instead of 4x
// by 4 loosely-synced column-tile CTAs (R6). Same step pattern, same moving
// ~3MB window, same 512B/warp shape as R6 - only row granularity changes.
// Epilogue: threads own distinct columns -> direct atomics into 8 replicas
// (R13-verified). Last CTA folds replicas -> scalar, re-zeros for replay.

#define COLS 1024
#define NCTAS 740           // 5 CTAs/SM, one wave
#define NREP 8
#define LN2 0.6931471805599453f

__device__ float g_part[NREP][3][COLS]; // [0]=sum x^2, [1]=sum x, [2]=sum x*log2(x)
__device__ unsigned int g_count;

__global__ __launch_bounds__(256, 5) void el_fused_kernel(const float* __restrict__ x,
                                                          float* __restrict__ out,
                                                          int rows) {
    const int tid = threadIdx.x;
    const int b   = blockIdx.x;

    const float4* __restrict__ p = (const float4*)x;
    // row r = b + NCTAS*i ; address = r*(COLS/4) + tid
    const float4* __restrict__ q = p + (long)b * (COLS / 4) + tid;
    const long step = (long)NCTAS * (COLS / 4);

    float s2[4] = {0.f, 0.f, 0.f, 0.f};
    float s1[4] = {0.f, 0.f, 0.f, 0.f};
    float sx[4] = {0.f, 0.f, 0.f, 0.f};

    const int iters = (rows - b + NCTAS - 1) / NCTAS;   // ~88-89
    const int it8   = iters & ~7;

    for (int i = 0; i < it8; i += 8) {
        // fixed trip count of 8: fully unrolled, 8 independent front-batched
        // float4 loads (the R6-validated shape; 48-reg budget at 5 CTAs/SM)
        #pragma unroll
        for (int u = 0; u < 8; u++) {
            float4 v = q[(long)u * step];
            float vv[4] = {v.x, v.y, v.z, v.w};
            #pragma unroll
            for (int k = 0; k < 4; k++) {
                float a = vv[k];
                s2[k] = fmaf(a, a, s2[k]);
                s1[k] += a;
                // x*log2(x): at a==0 this is fmaf(0, lg2(1e-37), s) == s
                float l = __log2f(fmaxf(a, 1e-37f));
                sx[k] = fmaf(a, l, sx[k]);
            }
        }
        q += 8 * step;
    }
    for (int i = it8; i < iters; i++) {
        float4 v = *q;
        q += step;
        float vv[4] = {v.x, v.y, v.z, v.w};
        #pragma unroll
        for (int k = 0; k < 4; k++) {
            float a = vv[k];
            s2[k] = fmaf(a, a, s2[k]);
            s1[k] += a;
            float l = __log2f(fmaxf(a, 1e-37f));
            sx[k] = fmaf(a, l, sx[k]);
        }
    }

    // every thread owns distinct columns -> direct atomics, replicated 8x
    {
        const int rep = b & (NREP - 1);
        #pragma unroll
        for (int k = 0; k < 4; k++) {
            atomicAdd(&g_part[rep][0][4 * tid + k], s2[k]);
            atomicAdd(&g_part[rep][1][4 * tid + k], s1[k]);
            atomicAdd(&g_part[rep][2][4 * tid + k], sx[k]);
        }
    }

    // ---- last CTA does the final combine ----
    __shared__ int amLast;
    __threadfence();
    __syncthreads();
    if (tid == 0) {
        unsigned v = atomicAdd(&g_count, 1u);
        amLast = (v == NCTAS - 1);
    }
    __syncthreads();
    if (!amLast) return;

    float acc = 0.f;
    #pragma unroll
    for (int m = 0; m < 4; m++) {
        const int j = tid + m * 256;
        float S2 = 0.f, S1 = 0.f, SX = 0.f;
        #pragma unroll
        for (int r = 0; r < NREP; r++) {
            S2 += __ldcg(&g_part[r][0][j]);
            S1 += __ldcg(&g_part[r][1][j]);
            SX += __ldcg(&g_part[r][2][j]);
        }
        float n = fmaxf(sqrtf(S2), 1e-12f);
        acc += (SX * LN2 - S1 * logf(n)) / n;
    }
    __syncthreads();   // all reads of g_part done before re-zero

    // re-zero all scratch for the next graph replay
    for (int i = tid; i < NREP * 3 * COLS; i += 256) ((float*)g_part)[i] = 0.0f;
    if (tid == 0) g_count = 0u;

    __shared__ float sm[256];
    sm[tid] = acc;
    __syncthreads();
    #pragma unroll
    for (int s = 128; s > 0; s >>= 1) {
        if (tid < s) sm[tid] += sm[tid + s];
        __syncthreads();
    }
    if (tid == 0) out[0] = -sm[0] / (float)rows;
}

extern "C" void kernel_launch(void* const* d_in, const int* in_sizes, int n_in,
                              void* d_out, int out_size) {
    const float* x = (const float*)d_in[0];
    int rows = in_sizes[0] / COLS;   // 65536
    el_fused_kernel<<<NCTAS, 256>>>(x, (float*)d_out, rows);
}

// round 15
// speedup vs baseline: 1.2385x; 1.2385x over previous
#include <cuda_runtime.h>
#include <math.h>

// EntropyLoss: x [R=65536, C=1024] f32 row-major.
//   n_j  = max( sqrt(sum_i x_ij^2), 1e-12 )
//   out  = -(1/R) * sum_j (1/n_j) * [ sum_i x*ln(x) - ln(n_j) * sum_i x ]
// (eps=1e-8 inside the reference log contributes <1e-6 relative error; dropped)
//
// R15 (final form): merge of the two best validated components.
//  - Mainloop/config: R6 (5 CTAs/SM, 48-reg budget, fixed-8 front-batched
//    float4 loads, grid-strided rows, GRID_Y=4 column tiles).
//  - Scheduling: R7 work-stealing over 32-row chunks per column tile
//    (prefetched grab; best measured bench of the session).
//  - Epilogue: smem 4-slice pre-reduction -> 768 atomics/CTA (R13/R14 proved
//    >1M direct atomics cost ~7.4ns each; 568K total is non-binding), then
//    R10 parallel per-tile combine + 4-way final add.
// All scratch/counters re-zeroed each call so graph replays start clean.

#define COLS 1024
#define GRID_X 185          // 185*4 = 740 CTAs = 5/SM, one wave
#define GRID_Y 4            // column tiles of 256
#define CHUNK_ROWS 32
#define LN2 0.6931471805599453f

__device__ float g_part[3][COLS];      // [0]=sum x^2, [1]=sum x, [2]=sum x*log2(x)
__device__ float g_tile[GRID_Y];
__device__ unsigned int g_tile_count[GRID_Y];
__device__ unsigned int g_work[GRID_Y];
__device__ unsigned int g_final;

__global__ __launch_bounds__(256, 5) void el_fused_kernel(const float* __restrict__ x,
                                                          float* __restrict__ out,
                                                          int rows) {
    const int tid     = threadIdx.x;
    const int cg      = tid & 63;     // 64 float4 column-groups per block (256 cols)
    const int slice   = tid >> 6;     // 4 row slices per block
    const int ty      = blockIdx.y;
    const int colbase = ty * 256;
    const int g4      = (colbase >> 2) + cg;   // float4 index within a row

    const float4* __restrict__ p = (const float4*)x;

    float s2[4] = {0.f, 0.f, 0.f, 0.f};
    float s1[4] = {0.f, 0.f, 0.f, 0.f};
    float sx[4] = {0.f, 0.f, 0.f, 0.f};

    const int nchunks = (rows + CHUNK_ROWS - 1) / CHUNK_ROWS;   // 2048

    __shared__ unsigned int sh_chunk;
    if (tid == 0) sh_chunk = atomicAdd(&g_work[ty], 1u);

    for (;;) {
        __syncthreads();
        const unsigned int c = sh_chunk;
        __syncthreads();
        if (c >= (unsigned)nchunks) break;
        // prefetch the next chunk id; L2 atomic latency hides under compute
        if (tid == 0) sh_chunk = atomicAdd(&g_work[ty], 1u);

        const long base = (long)(c * CHUNK_ROWS + slice) * (COLS / 4) + g4;

        if ((int)(c + 1) * CHUNK_ROWS <= rows) {
            // full chunk: 8 independent loads, fully unrolled -> front-batched
            #pragma unroll
            for (int u = 0; u < 8; u++) {
                float4 v = p[base + (long)u * (4 * (COLS / 4))];
                float vv[4] = {v.x, v.y, v.z, v.w};
                #pragma unroll
                for (int k = 0; k < 4; k++) {
                    float a = vv[k];
                    s2[k] = fmaf(a, a, s2[k]);
                    s1[k] += a;
                    // x*log2(x): at a==0 -> fmaf(0, lg2(1e-37), s) == s
                    float l = __log2f(fmaxf(a, 1e-37f));
                    sx[k] = fmaf(a, l, sx[k]);
                }
            }
        } else {
            // ragged last chunk (not hit for rows=65536)
            #pragma unroll
            for (int u = 0; u < 8; u++) {
                int r = (int)c * CHUNK_ROWS + slice + 4 * u;
                if (r < rows) {
                    float4 v = p[(long)r * (COLS / 4) + g4];
                    float vv[4] = {v.x, v.y, v.z, v.w};
                    #pragma unroll
                    for (int k = 0; k < 4; k++) {
                        float a = vv[k];
                        s2[k] = fmaf(a, a, s2[k]);
                        s1[k] += a;
                        float l = __log2f(fmaxf(a, 1e-37f));
                        sx[k] = fmaf(a, l, sx[k]);
                    }
                }
            }
        }
    }

    // Reduce the 4 row-slices within the block before touching L2 atomics.
    __shared__ float red[4][64 * 12];
    #pragma unroll
    for (int k = 0; k < 4; k++) {
        red[slice][cg * 12 + 0 + k] = s2[k];
        red[slice][cg * 12 + 4 + k] = s1[k];
        red[slice][cg * 12 + 8 + k] = sx[k];
    }
    __syncthreads();

    for (int i = tid; i < 64 * 12; i += 256) {
        float t = red[0][i] + red[1][i] + red[2][i] + red[3][i];
        int cg2  = i / 12;
        int comp = i % 12;
        int type = comp >> 2;     // 0: x^2, 1: x, 2: x*log2(x)
        int sub  = comp & 3;
        int col  = colbase + cg2 * 4 + sub;
        atomicAdd(&g_part[type][col], t);
    }

    // ---- per-tile last block: combine this tile's 256 columns ----
    __shared__ int amTileLast;
    __threadfence();
    __syncthreads();
    if (tid == 0) {
        unsigned v = atomicAdd(&g_tile_count[ty], 1u);
        amTileLast = (v == GRID_X - 1);
    }
    __syncthreads();
    if (!amTileLast) return;

    {
        const int j = colbase + tid;   // each thread owns one column of the tile
        float S2 = __ldcg(&g_part[0][j]);
        float S1 = __ldcg(&g_part[1][j]);
        float SX = __ldcg(&g_part[2][j]);
        float n  = fmaxf(sqrtf(S2), 1e-12f);
        float t  = (SX * LN2 - S1 * logf(n)) / n;

        // re-zero this tile's scratch + work counter for the next graph replay
        g_part[0][j] = 0.0f;
        g_part[1][j] = 0.0f;
        g_part[2][j] = 0.0f;
        if (tid == 0) { g_tile_count[ty] = 0u; g_work[ty] = 0u; }

        __shared__ float sm[256];
        sm[tid] = t;
        __syncthreads();
        #pragma unroll
        for (int s = 128; s > 0; s >>= 1) {
            if (tid < s) sm[tid] += sm[tid + s];
            __syncthreads();
        }
        if (tid == 0) g_tile[ty] = sm[0];
    }

    // ---- global last tile writes the output ----
    __shared__ int amFinal;
    __threadfence();
    __syncthreads();
    if (tid == 0) {
        unsigned v = atomicAdd(&g_final, 1u);
        amFinal = (v == GRID_Y - 1);
    }
    __syncthreads();
    if (!amFinal) return;

    if (tid == 0) {
        float s = 0.f;
        #pragma unroll
        for (int m = 0; m < GRID_Y; m++) s += __ldcg(&g_tile[m]);
        out[0] = -s / (float)rows;
        g_final = 0u;
    }
}

extern "C" void kernel_launch(void* const* d_in, const int* in_sizes, int n_in,
                              void* d_out, int out_size) {
    const float* x = (const float*)d_in[0];
    int rows = in_sizes[0] / COLS;   // 65536
    dim3 grid(GRID_X, GRID_Y);
    el_fused_kernel<<<grid, 256>>>(x, (float*)d_out, rows);
}

// round 16
// speedup vs baseline: 1.2660x; 1.0222x over previous
#include <cuda_runtime.h>
#include <math.h>

// EntropyLoss: x [R=65536, C=1024] f32 row-major.
//   n_j  = max( sqrt(sum_i x_ij^2), 1e-12 )
//   out  = -(1/R) * sum_j (1/n_j) * [ sum_i x*ln(x) - ln(n_j) * sum_i x ]
// (eps=1e-8 inside the reference log contributes <1e-6 relative error; dropped)
//
// R16: R6 mainloop (5 CTAs/SM, 48-reg budget, fixed-8 front-batched float4
// loads, grid-strided rows, 4 column tiles) + R10 parallel per-tile tail,
// with the s2/s1 accumulations packed into Blackwell f32x2 instructions
// (fma.rn.f32x2 / add.rn.f32x2, PTX-only): 10 -> 8 instrs per 2 elements,
// freeing issue slots so the 8-load front batch dispatches earlier each
// iteration. Session evidence: all healthy configs sit at the ~5.9 TB/s
// streaming equilibrium; this targets the last non-memory coupling.
// All scratch/counters re-zeroed each call for clean graph replays.

#define COLS 1024
#define GRID_X 185          // 185*4 = 740 CTAs = 5/SM, one wave
#define GRID_Y 4            // column tiles of 256
#define LN2 0.6931471805599453f

__device__ float g_part[3][COLS];      // [0]=sum x^2, [1]=sum x, [2]=sum x*log2(x)
__device__ float g_tile[GRID_Y];
__device__ unsigned int g_tile_count[GRID_Y];
__device__ unsigned int g_final;

__device__ __forceinline__ unsigned long long pack2(float lo, float hi) {
    unsigned long long r;
    asm("mov.b64 %0, {%1, %2};" : "=l"(r) : "f"(lo), "f"(hi));
    return r;
}
__device__ __forceinline__ void unpack2(unsigned long long v, float& lo, float& hi) {
    asm("mov.b64 {%0, %1}, %2;" : "=f"(lo), "=f"(hi) : "l"(v));
}
__device__ __forceinline__ void fma2_acc(unsigned long long& acc, unsigned long long a) {
    asm("fma.rn.f32x2 %0, %1, %2, %0;" : "+l"(acc) : "l"(a), "l"(a));
}
__device__ __forceinline__ void add2_acc(unsigned long long& acc, unsigned long long a) {
    asm("add.rn.f32x2 %0, %1, %0;" : "+l"(acc) : "l"(a));
}

__global__ __launch_bounds__(256, 5) void el_fused_kernel(const float* __restrict__ x,
                                                          float* __restrict__ out,
                                                          int rows) {
    const int tid     = threadIdx.x;
    const int cg      = tid & 63;     // 64 float4 column-groups per block (256 cols)
    const int slice   = tid >> 6;     // 4 row slices per block
    const int ty      = blockIdx.y;
    const int colbase = ty * 256;
    const int g4      = (colbase >> 2) + cg;   // float4 index within a row

    const float4* __restrict__ p = (const float4*)x;

    unsigned long long S2p[2] = {0ull, 0ull};  // packed {s2[0],s2[1]},{s2[2],s2[3]}
    unsigned long long S1p[2] = {0ull, 0ull};  // packed sums of x
    float sx[4] = {0.f, 0.f, 0.f, 0.f};

    const int  rstride = GRID_X * 4;                 // 740 row slices total
    const int  r0      = blockIdx.x * 4 + slice;
    const long step    = (long)rstride * (COLS / 4);
    const float4* __restrict__ q = p + (long)r0 * (COLS / 4) + g4;

    const int iters = (rows - r0 + rstride - 1) / rstride;   // ~88-89
    const int it8   = iters & ~7;

    for (int b = 0; b < it8; b += 8) {
        // fixed trip count of 8: fully unrolled, 8 independent front-batched
        // float4 loads (the validated R6 shape)
        #pragma unroll
        for (int u = 0; u < 8; u++) {
            float4 v = q[(long)u * step];
            // packed accumulation: x^2 and x, two lanes per instruction
            unsigned long long a01 = pack2(v.x, v.y);
            unsigned long long a23 = pack2(v.z, v.w);
            fma2_acc(S2p[0], a01);  fma2_acc(S2p[1], a23);
            add2_acc(S1p[0], a01);  add2_acc(S1p[1], a23);
            // x*log2(x): at a==0 this is fmaf(0, lg2(1e-37), s) == s
            float vv[4] = {v.x, v.y, v.z, v.w};
            #pragma unroll
            for (int k = 0; k < 4; k++) {
                float a = vv[k];
                float l = __log2f(fmaxf(a, 1e-37f));
                sx[k] = fmaf(a, l, sx[k]);
            }
        }
        q += 8 * step;
    }
    for (int i = it8; i < iters; i++) {
        float4 v = *q;
        q += step;
        unsigned long long a01 = pack2(v.x, v.y);
        unsigned long long a23 = pack2(v.z, v.w);
        fma2_acc(S2p[0], a01);  fma2_acc(S2p[1], a23);
        add2_acc(S1p[0], a01);  add2_acc(S1p[1], a23);
        float vv[4] = {v.x, v.y, v.z, v.w};
        #pragma unroll
        for (int k = 0; k < 4; k++) {
            float a = vv[k];
            float l = __log2f(fmaxf(a, 1e-37f));
            sx[k] = fmaf(a, l, sx[k]);
        }
    }

    float s2[4], s1[4];
    unpack2(S2p[0], s2[0], s2[1]);  unpack2(S2p[1], s2[2], s2[3]);
    unpack2(S1p[0], s1[0], s1[1]);  unpack2(S1p[1], s1[2], s1[3]);

    // Reduce the 4 row-slices within the block before touching L2 atomics.
    __shared__ float red[4][64 * 12];
    #pragma unroll
    for (int k = 0; k < 4; k++) {
        red[slice][cg * 12 + 0 + k] = s2[k];
        red[slice][cg * 12 + 4 + k] = s1[k];
        red[slice][cg * 12 + 8 + k] = sx[k];
    }
    __syncthreads();

    for (int i = tid; i < 64 * 12; i += 256) {
        float t = red[0][i] + red[1][i] + red[2][i] + red[3][i];
        int cg2  = i / 12;
        int comp = i % 12;
        int type = comp >> 2;     // 0: x^2, 1: x, 2: x*log2(x)
        int sub  = comp & 3;
        int col  = colbase + cg2 * 4 + sub;
        atomicAdd(&g_part[type][col], t);
    }

    // ---- per-tile last block: combine this tile's 256 columns ----
    __shared__ int amTileLast;
    __threadfence();
    __syncthreads();
    if (tid == 0) {
        unsigned v = atomicAdd(&g_tile_count[ty], 1u);
        amTileLast = (v == GRID_X - 1);
    }
    __syncthreads();
    if (!amTileLast) return;

    {
        const int j = colbase + tid;   // each thread owns one column of the tile
        float S2 = __ldcg(&g_part[0][j]);
        float S1 = __ldcg(&g_part[1][j]);
        float SX = __ldcg(&g_part[2][j]);
        float n  = fmaxf(sqrtf(S2), 1e-12f);
        float t  = (SX * LN2 - S1 * logf(n)) / n;

        // re-zero this tile's scratch for the next graph replay
        g_part[0][j] = 0.0f;
        g_part[1][j] = 0.0f;
        g_part[2][j] = 0.0f;
        if (tid == 0) g_tile_count[ty] = 0u;

        __shared__ float sm[256];
        sm[tid] = t;
        __syncthreads();
        #pragma unroll
        for (int s = 128; s > 0; s >>= 1) {
            if (tid < s) sm[tid] += sm[tid + s];
            __syncthreads();
        }
        if (tid == 0) g_tile[ty] = sm[0];
    }

    // ---- global last tile writes the output ----
    __shared__ int amFinal;
    __threadfence();
    __syncthreads();
    if (tid == 0) {
        unsigned v = atomicAdd(&g_final, 1u);
        amFinal = (v == GRID_Y - 1);
    }
    __syncthreads();
    if (!amFinal) return;

    if (tid == 0) {
        float s = 0.f;
        #pragma unroll
        for (int m = 0; m < GRID_Y; m++) s += __ldcg(&g_tile[m]);
        out[0] = -s / (float)rows;
        g_final = 0u;
    }
}

extern "C" void kernel_launch(void* const* d_in, const int* in_sizes, int n_in,
                              void* d_out, int out_size) {
    const float* x = (const float*)d_in[0];
    int rows = in_sizes[0] / COLS;   // 65536
    dim3 grid(GRID_X, GRID_Y);
    el_fused_kernel<<<grid, 256>>>(x, (float*)d_out, rows);
}